// round 1
// baseline (speedup 1.0000x reference)
#include <cuda_runtime.h>
#include <math.h>

#define NROWS 32768
#define FDIM  128
#define KDIM  64
#define MNBR  32

// Scratch (allocation-free rule: __device__ globals)
__device__ float g_xi [NROWS*FDIM];
__device__ float g_xjp[NROWS*FDIM];
__device__ float g_m0 [NROWS*FDIM];
__device__ float g_m1 [NROWS*FDIM];
__device__ float g_t  [NROWS*FDIM];

__device__ __forceinline__ float sspf(float a) {
    // shifted softplus: log1p(exp(a)) - log(2), numerically stable
    return fmaxf(a, 0.0f) + log1pf(expf(-fabsf(a))) - 0.69314718055994530942f;
}

// Generic row GEMM: out[n,f] = epilogue( sum_k act(in[n,k]) * W[f,k] + b[f] )
// Thread f holds W row f (128 regs). Activations broadcast from smem (LDS.128).
template<bool IN_SSP, bool ADD, bool MULVEC>
__global__ __launch_bounds__(128, 3) void rowgemm(
    const float* __restrict__ in, const float* __restrict__ W,
    const float* __restrict__ bias, const float* __restrict__ addp,
    const float* __restrict__ mulv, float* __restrict__ out)
{
    __shared__ float xs[8 * FDIM];
    const int f = threadIdx.x;

    float w[FDIM];
    {
        const float4* W4 = (const float4*)(W + f * FDIM);
        #pragma unroll
        for (int i = 0; i < FDIM / 4; i++) {
            float4 v = W4[i];
            w[4*i] = v.x; w[4*i+1] = v.y; w[4*i+2] = v.z; w[4*i+3] = v.w;
        }
    }
    const float bf = bias[f];
    const float mv = MULVEC ? mulv[f] : 1.0f;

    const int ntiles = NROWS / 8;
    for (int tile = blockIdx.x; tile < ntiles; tile += gridDim.x) {
        const int r0 = tile * 8;
        const float4* inp = (const float4*)(in + r0 * FDIM);
        float4* xs4 = (float4*)xs;
        #pragma unroll
        for (int i = 0; i < 2; i++) {
            float4 v = inp[f + 128 * i];
            if (IN_SSP) { v.x = sspf(v.x); v.y = sspf(v.y); v.z = sspf(v.z); v.w = sspf(v.w); }
            xs4[f + 128 * i] = v;
        }
        __syncthreads();
        for (int r = 0; r < 8; r++) {
            const float4* xr = (const float4*)(xs + r * FDIM);
            float a0 = 0.f, a1 = 0.f, a2 = 0.f, a3 = 0.f;
            #pragma unroll
            for (int kk = 0; kk < FDIM / 4; kk++) {
                float4 v = xr[kk];
                a0 += v.x * w[4*kk];   a1 += v.y * w[4*kk+1];
                a2 += v.z * w[4*kk+2]; a3 += v.w * w[4*kk+3];
            }
            float o = bf + ((a0 + a1) + (a2 + a3));
            const int n = r0 + r;
            if (ADD) o += addp[n * FDIM + f] * mv;
            out[n * FDIM + f] = o;
        }
        __syncthreads();
    }
}

// Fused per-atom: edge filter GEMM (k2f weights in regs) + gather + attention.
// xj[e,f] = (rbf[e,:] @ k2f_w[f,:]) * xj_pre[idx_j[e], f]
// logits use the faithful reshape: logit[m2] = sum_f2 xi[f2] * slab_flat[f2*32+m2]
// m_out[f] = xi[f] + sum_m att[m] * slab[m][f]
__global__ __launch_bounds__(128, 4) void attn_kernel(
    const float* __restrict__ rbf, const int* __restrict__ idxj,
    const float* __restrict__ k2f, const float* __restrict__ xi,
    const float* __restrict__ xjp, float* __restrict__ mout)
{
    __shared__ float rbf_sm[MNBR * KDIM];   // 8 KB, contiguous per atom
    __shared__ float xj_sm[MNBR * FDIM];    // 16 KB slab, flat = (m,f) row-major
    __shared__ float xi_sm[FDIM];
    __shared__ float part_sm[4 * 32];
    __shared__ float att_sm[MNBR];
    __shared__ int   jidx[MNBR];

    const int f = threadIdx.x;

    float w[KDIM];
    {
        const float4* W4 = (const float4*)(k2f + f * KDIM);
        #pragma unroll
        for (int i = 0; i < KDIM / 4; i++) {
            float4 v = W4[i];
            w[4*i] = v.x; w[4*i+1] = v.y; w[4*i+2] = v.z; w[4*i+3] = v.w;
        }
    }

    for (int n = blockIdx.x; n < NROWS; n += gridDim.x) {
        // load this atom's 32 rbf rows (contiguous 8 KB) + neighbor indices + xi row
        const float4* rp = (const float4*)(rbf + (size_t)n * MNBR * KDIM);
        #pragma unroll
        for (int i = 0; i < 4; i++) ((float4*)rbf_sm)[f + 128 * i] = rp[f + 128 * i];
        if (f < MNBR) jidx[f] = idxj[n * MNBR + f];
        const float xif = xi[n * FDIM + f];
        xi_sm[f] = xif;
        __syncthreads();

        // edge loop: g = rbf@k2f.T (regs), multiply by gathered xj_pre (prefetched)
        float xp_next = xjp[(size_t)jidx[0] * FDIM + f];
        #pragma unroll 2
        for (int m = 0; m < MNBR; m++) {
            float xp = xp_next;
            if (m + 1 < MNBR) xp_next = xjp[(size_t)jidx[m + 1] * FDIM + f];
            const float4* rr = (const float4*)(rbf_sm + m * KDIM);
            float a0 = 0.f, a1 = 0.f, a2 = 0.f, a3 = 0.f;
            #pragma unroll
            for (int kk = 0; kk < KDIM / 4; kk++) {
                float4 v = rr[kk];
                a0 += v.x * w[4*kk];   a1 += v.y * w[4*kk+1];
                a2 += v.z * w[4*kk+2]; a3 += v.w * w[4*kk+3];
            }
            xj_sm[m * FDIM + f] = ((a0 + a1) + (a2 + a3)) * xp;
        }
        __syncthreads();

        // attention logits via the flat reshape; bank = m2 = lane -> conflict-free
        {
            const int m2 = f & 31, q = f >> 5;
            float s = 0.f;
            #pragma unroll
            for (int i = 0; i < 32; i++) {
                const int f2 = q * 32 + i;
                s += xi_sm[f2] * xj_sm[f2 * 32 + m2];
            }
            part_sm[q * 32 + m2] = s;
        }
        __syncthreads();

        if (f < 32) {
            float lg = part_sm[f] + part_sm[32 + f] + part_sm[64 + f] + part_sm[96 + f];
            float mx = lg;
            #pragma unroll
            for (int off = 16; off; off >>= 1)
                mx = fmaxf(mx, __shfl_xor_sync(0xffffffffu, mx, off));
            float e = expf(lg - mx);
            float sm = e;
            #pragma unroll
            for (int off = 16; off; off >>= 1)
                sm += __shfl_xor_sync(0xffffffffu, sm, off);
            att_sm[f] = e / sm;
        }
        __syncthreads();

        // weighted sum over neighbors
        float acc = xif;
        #pragma unroll
        for (int m = 0; m < MNBR; m++) acc += att_sm[m] * xj_sm[m * FDIM + f];
        mout[(size_t)n * FDIM + f] = acc;
        __syncthreads();   // protect smem reuse for next atom
    }
}

extern "C" void kernel_launch(void* const* d_in, const int* in_sizes, int n_in,
                              void* d_out, int out_size)
{
    const float* x    = (const float*)d_in[0];
    const float* rbf  = (const float*)d_in[1];
    // d_in[2] = idx_i: unused by the reference
    const int*   idxj = (const int*)  d_in[3];
    const float* k2f  = (const float*)d_in[4];
    const float* wi   = (const float*)d_in[5];
    const float* bi   = (const float*)d_in[6];
    const float* wj   = (const float*)d_in[7];
    const float* bj   = (const float*)d_in[8];
    const float* rw1  = (const float*)d_in[9];
    const float* rb1  = (const float*)d_in[10];
    const float* rw2  = (const float*)d_in[11];
    const float* rb2  = (const float*)d_in[12];
    const float* wd   = (const float*)d_in[13];
    const float* bd   = (const float*)d_in[14];
    const float* u    = (const float*)d_in[15];
    float* out = (float*)d_out;

    float *xi_p, *xjp_p, *m0_p, *m1_p, *t_p;
    cudaGetSymbolAddress((void**)&xi_p,  g_xi);
    cudaGetSymbolAddress((void**)&xjp_p, g_xjp);
    cudaGetSymbolAddress((void**)&m0_p,  g_m0);
    cudaGetSymbolAddress((void**)&m1_p,  g_m1);
    cudaGetSymbolAddress((void**)&t_p,   g_t);

    const int GG = 444;  // 148 SMs * 3 blocks, grid-stride over row tiles
    const int GA = 592;  // 148 SMs * 4 blocks, grid-stride over atoms

    // xi = ssp(x) @ wi.T + bi ; xj_pre = ssp(x) @ wj.T + bj
    rowgemm<true,  false, false><<<GG, 128>>>(x,    wi, bi, nullptr, nullptr, xi_p);
    rowgemm<true,  false, false><<<GG, 128>>>(x,    wj, bj, nullptr, nullptr, xjp_p);

    // m0 = xi + attention-weighted neighbor aggregation
    attn_kernel<<<GA, 128>>>(rbf, idxj, k2f, xi_p, xjp_p, m0_p);

    // residual block 0: m1 = m0 + (ssp(m0)@w1.T+b1)@w2.T+b2
    rowgemm<true,  false, false><<<GG, 128>>>(m0_p, rw1,               rb1,        nullptr, nullptr, t_p);
    rowgemm<false, true,  false><<<GG, 128>>>(t_p,  rw2,               rb2,        m0_p,    nullptr, m1_p);

    // residual block 1: m0 = m1 + (ssp(m1)@w1'.T+b1')@w2'.T+b2'
    rowgemm<true,  false, false><<<GG, 128>>>(m1_p, rw1 + FDIM*FDIM,   rb1 + FDIM, nullptr, nullptr, t_p);
    rowgemm<false, true,  false><<<GG, 128>>>(t_p,  rw2 + FDIM*FDIM,   rb2 + FDIM, m1_p,    nullptr, m0_p);

    // out = u*x + ssp(m0) @ wd.T + bd
    rowgemm<true,  true,  true ><<<GG, 128>>>(m0_p, wd,                bd,         x,       u,       out);
}